// round 1
// baseline (speedup 1.0000x reference)
#include <cuda_runtime.h>
#include <cstdint>

#define B_   8192
#define NN   40
#define FF   256
#define NBLKC 4
#define BLKC 10

// ---------------- scratch (device globals: allocation-free) ----------------
__device__ float g_t[(size_t)B_ * NN * FF];     // t = blockdiag(adj) @ input, layout [n][b][k]
__device__ float g_y[(size_t)B_ * NN * FF];     // y = t @ W, layout [n][b][f]
__device__ float g_sum[NN * FF];
__device__ float g_sumsq[NN * FF];
__device__ float g_a[NN * FF];
__device__ float g_c[NN * FF];

// ---------------- helpers ----------------
__device__ __forceinline__ uint32_t f2tf32(float x) {
    uint32_t d;
    asm("cvt.rna.tf32.f32 %0, %1;" : "=r"(d) : "f"(x));
    return d;
}

__device__ __forceinline__ void mma_tf32(float* c, const uint32_t* a, const uint32_t* b) {
    asm volatile(
        "mma.sync.aligned.m16n8k8.row.col.f32.tf32.tf32.f32 "
        "{%0,%1,%2,%3}, {%4,%5,%6,%7}, {%8,%9}, {%0,%1,%2,%3};"
        : "+f"(c[0]), "+f"(c[1]), "+f"(c[2]), "+f"(c[3])
        : "r"(a[0]), "r"(a[1]), "r"(a[2]), "r"(a[3]),
          "r"(b[0]), "r"(b[1]));
}

// ---------------- k0: zero stats ----------------
__global__ void k0_zero() {
    int i = blockIdx.x * blockDim.x + threadIdx.x;
    if (i < NN * FF) { g_sum[i] = 0.f; g_sumsq[i] = 0.f; }
}

// ---------------- k1: t = blockdiag(adj) @ input, write n-major ----------------
__global__ void k1_block(const float* __restrict__ input, const float* __restrict__ adj) {
    int b   = blockIdx.x;
    int blk = blockIdx.y;
    int s   = blk * BLKC;
    __shared__ float s_in[BLKC][FF];
    __shared__ float s_adj[BLKC][BLKC];
    int tid = threadIdx.x;

    const float* ip = input + ((size_t)b * NN + s) * FF;
#pragma unroll
    for (int r = 0; r < BLKC; r++) s_in[r][tid] = ip[(size_t)r * FF + tid];
    if (tid < BLKC * BLKC) {
        int r = tid / BLKC, c = tid % BLKC;
        s_adj[r][c] = adj[((size_t)b * NN + s + r) * NN + s + c];
    }
    __syncthreads();

#pragma unroll
    for (int r = 0; r < BLKC; r++) {
        float acc = 0.f;
#pragma unroll
        for (int j = 0; j < BLKC; j++) acc += s_adj[r][j] * s_in[j][tid];
        g_t[((size_t)(s + r) * B_ + b) * FF + tid] = acc;
    }
}

// ---------------- k2: y = t @ W  (tf32 mma.sync), tile 128x256x256 ----------------
#define BM 128
#define BK 32
#define AS_STRIDE 36      // 128x32 fp32(as tf32 bits), padded
#define BS_STRIDE 264     // 32x256, padded for conflict-free frag loads
#define K2_SMEM_BYTES ((BM * AS_STRIDE + BK * BS_STRIDE) * 4)

__global__ void __launch_bounds__(256, 1) k2_gemm(const float* __restrict__ W) {
    extern __shared__ float smem[];
    float* As = smem;                      // [BM][AS_STRIDE]
    float* Bs = smem + BM * AS_STRIDE;     // [BK][BS_STRIDE]

    int n  = blockIdx.y;
    int b0 = blockIdx.x * BM;
    int tid  = threadIdx.x;
    int warp = tid >> 5, lane = tid & 31;
    int g = lane >> 2, tg = lane & 3;
    int wm = warp >> 2, wn = warp & 3;     // wm: 0..1 (64 rows), wn: 0..3 (64 cols)

    const float* Abase = g_t + ((size_t)n * B_ + b0) * FF;

    float acc[4][8][4];
#pragma unroll
    for (int mt = 0; mt < 4; mt++)
#pragma unroll
        for (int nt = 0; nt < 8; nt++)
#pragma unroll
            for (int r = 0; r < 4; r++) acc[mt][nt][r] = 0.f;

    for (int kt = 0; kt < FF / BK; kt++) {
        int k0 = kt * BK;
        __syncthreads();
        // stage A tile: 128 rows x 32 k  (1024 float4 / 256 thr = 4 each)
#pragma unroll
        for (int it = 0; it < 4; it++) {
            int idx = tid + it * 256;
            int row = idx >> 3, c4 = (idx & 7) * 4;
            float4 v = *(const float4*)(Abase + (size_t)row * FF + k0 + c4);
            float* dst = As + row * AS_STRIDE + c4;
            dst[0] = __uint_as_float(f2tf32(v.x));
            dst[1] = __uint_as_float(f2tf32(v.y));
            dst[2] = __uint_as_float(f2tf32(v.z));
            dst[3] = __uint_as_float(f2tf32(v.w));
        }
        // stage B tile: 32 k x 256 f  (2048 float4 / 256 thr = 8 each)
#pragma unroll
        for (int it = 0; it < 8; it++) {
            int idx = tid + it * 256;
            int kr = idx >> 6, f4 = (idx & 63) * 4;
            float4 v = *(const float4*)(W + (size_t)(k0 + kr) * FF + f4);
            float* dst = Bs + kr * BS_STRIDE + f4;
            dst[0] = __uint_as_float(f2tf32(v.x));
            dst[1] = __uint_as_float(f2tf32(v.y));
            dst[2] = __uint_as_float(f2tf32(v.z));
            dst[3] = __uint_as_float(f2tf32(v.w));
        }
        __syncthreads();

#pragma unroll
        for (int k8 = 0; k8 < BK / 8; k8++) {
            int kk = k8 * 8;
            uint32_t afr[4][4], bfr[8][2];
#pragma unroll
            for (int mt = 0; mt < 4; mt++) {
                int m = wm * 64 + mt * 16;
                afr[mt][0] = __float_as_uint(As[(m + g)     * AS_STRIDE + kk + tg]);
                afr[mt][1] = __float_as_uint(As[(m + g + 8) * AS_STRIDE + kk + tg]);
                afr[mt][2] = __float_as_uint(As[(m + g)     * AS_STRIDE + kk + tg + 4]);
                afr[mt][3] = __float_as_uint(As[(m + g + 8) * AS_STRIDE + kk + tg + 4]);
            }
#pragma unroll
            for (int nt = 0; nt < 8; nt++) {
                int f = wn * 64 + nt * 8 + g;
                bfr[nt][0] = __float_as_uint(Bs[(kk + tg)     * BS_STRIDE + f]);
                bfr[nt][1] = __float_as_uint(Bs[(kk + tg + 4) * BS_STRIDE + f]);
            }
#pragma unroll
            for (int mt = 0; mt < 4; mt++)
#pragma unroll
                for (int nt = 0; nt < 8; nt++)
                    mma_tf32(acc[mt][nt], afr[mt], bfr[nt]);
        }
    }

    // epilogue: write raw y (pre-BN)
#pragma unroll
    for (int mt = 0; mt < 4; mt++) {
        int m = wm * 64 + mt * 16;
#pragma unroll
        for (int nt = 0; nt < 8; nt++) {
            int f = wn * 64 + nt * 8 + 2 * tg;
            float2 v0 = make_float2(acc[mt][nt][0], acc[mt][nt][1]);
            float2 v1 = make_float2(acc[mt][nt][2], acc[mt][nt][3]);
            *(float2*)(g_y + ((size_t)n * B_ + b0 + m + g)     * FF + f) = v0;
            *(float2*)(g_y + ((size_t)n * B_ + b0 + m + g + 8) * FF + f) = v1;
        }
    }
}

// ---------------- k2b: batch stats per (n,f) ----------------
__global__ void k2b_stats() {
    int n = blockIdx.x;
    int bstart = blockIdx.y * 512;
    int f = threadIdx.x;
    const float* yp = g_y + ((size_t)n * B_ + bstart) * FF + f;
    float s = 0.f, s2 = 0.f;
    for (int i = 0; i < 512; i++) {
        float v = yp[(size_t)i * FF];
        s  += v;
        s2 += v * v;
    }
    atomicAdd(&g_sum[n * FF + f], s);
    atomicAdd(&g_sumsq[n * FF + f], s2);
}

// ---------------- k3: fold BN into per-feature affine (a, c) ----------------
__global__ void k3_coeff(const float* __restrict__ gamma, const float* __restrict__ beta) {
    int idx = blockIdx.x * 256 + threadIdx.x;
    if (idx >= NN * FF) return;
    int nrow = idx / FF;
    int blk  = nrow / BLKC;
    float mean = g_sum[idx] * (1.f / B_);
    float var  = g_sumsq[idx] * (1.f / B_) - mean * mean;
    float a = gamma[(size_t)blk * (NN * FF) + idx] * rsqrtf(var + 1e-5f);
    float bsum = 0.f;
#pragma unroll
    for (int i = 0; i < NBLKC; i++) bsum += beta[(size_t)i * (NN * FF) + idx];
    g_a[idx] = a;
    g_c[idx] = bsum - mean * a;
}

// ---------------- k4: out[b][n][f] = y[n][b][f]*a + c ----------------
__global__ void k4_out(float* __restrict__ out) {
    int n  = blockIdx.x;
    int b0 = blockIdx.y * 8;
    int f  = threadIdx.x;
    float a = g_a[n * FF + f];
    float c = g_c[n * FF + f];
#pragma unroll
    for (int r = 0; r < 8; r++) {
        float v = g_y[((size_t)n * B_ + b0 + r) * FF + f];
        out[((size_t)(b0 + r) * NN + n) * FF + f] = v * a + c;
    }
}

// ---------------- launch ----------------
extern "C" void kernel_launch(void* const* d_in, const int* in_sizes, int n_in,
                              void* d_out, int out_size) {
    const float* input = (const float*)d_in[0];
    const float* adj   = (const float*)d_in[1];
    const float* W     = (const float*)d_in[2];
    const float* gamma = (const float*)d_in[3];
    const float* beta  = (const float*)d_in[4];
    float* out = (float*)d_out;

    cudaFuncSetAttribute(k2_gemm, cudaFuncAttributeMaxDynamicSharedMemorySize, K2_SMEM_BYTES);

    k0_zero<<<(NN * FF + 255) / 256, 256>>>();
    k1_block<<<dim3(B_, NBLKC), FF>>>(input, adj);
    k2_gemm<<<dim3(B_ / BM, NN), 256, K2_SMEM_BYTES>>>(W);
    k2b_stats<<<dim3(NN, B_ / 512), FF>>>();
    k3_coeff<<<(NN * FF + 255) / 256, 256>>>(gamma, beta);
    k4_out<<<dim3(NN, B_ / 8), FF>>>(out);
}

// round 2
// speedup vs baseline: 1.2303x; 1.2303x over previous
#include <cuda_runtime.h>
#include <cstdint>

#define B_    8192
#define NN    40
#define FF    256
#define NBLKC 4
#define BLKC  10

// ---------------- scratch (device globals: allocation-free) ----------------
__device__ float g_sup[(size_t)B_ * NN * FF];   // support = input @ W, layout [b*40+n][f]
__device__ float g_sum[NN * FF];
__device__ float g_sumsq[NN * FF];
__device__ float g_a[NN * FF];
__device__ float g_c[NN * FF];

// ---------------- helpers ----------------
__device__ __forceinline__ void mma_tf32(float* c, const uint32_t* a, const uint32_t* b) {
    asm volatile(
        "mma.sync.aligned.m16n8k8.row.col.f32.tf32.tf32.f32 "
        "{%0,%1,%2,%3}, {%4,%5,%6,%7}, {%8,%9}, {%0,%1,%2,%3};"
        : "+f"(c[0]), "+f"(c[1]), "+f"(c[2]), "+f"(c[3])
        : "r"(a[0]), "r"(a[1]), "r"(a[2]), "r"(a[3]),
          "r"(b[0]), "r"(b[1]));
}

__device__ __forceinline__ void cp16(uint32_t dst, const void* src) {
    asm volatile("cp.async.cg.shared.global [%0], [%1], 16;" :: "r"(dst), "l"(src));
}
__device__ __forceinline__ void cp_commit() {
    asm volatile("cp.async.commit_group;");
}

// ---------------- k0: zero stats ----------------
__global__ void k0_zero() {
    int i = blockIdx.x * blockDim.x + threadIdx.x;
    if (i < NN * FF) { g_sum[i] = 0.f; g_sumsq[i] = 0.f; }
}

// ---------------- k2: support = input @ W  (tf32 mma.sync, cp.async double-buffer) ----
#define BM 128
#define BK 32
#define AS_STRIDE 36
#define BS_STRIDE 264
#define BUF_FLOATS (BM * AS_STRIDE + BK * BS_STRIDE)
#define K2_SMEM_BYTES (2 * BUF_FLOATS * 4)

__global__ void __launch_bounds__(256, 1) k2_gemm(const float* __restrict__ input,
                                                  const float* __restrict__ W) {
    extern __shared__ float smem[];
    uint32_t smem_u = (uint32_t)__cvta_generic_to_shared(smem);

    int b0 = blockIdx.x * BM;            // row in [0, 327680)
    int tid  = threadIdx.x;
    int warp = tid >> 5, lane = tid & 31;
    int g = lane >> 2, tg = lane & 3;
    int wm = warp >> 2, wn = warp & 3;   // warptile 64x64

    const float* Abase = input + (size_t)b0 * FF;

    float acc[4][8][4];
#pragma unroll
    for (int mt = 0; mt < 4; mt++)
#pragma unroll
        for (int nt = 0; nt < 8; nt++)
#pragma unroll
            for (int r = 0; r < 4; r++) acc[mt][nt][r] = 0.f;

    // stage tile kt into buffer buf
    auto stage = [&](int buf, int kt) {
        int k0 = kt * BK;
        uint32_t abuf = smem_u + (uint32_t)buf * BUF_FLOATS * 4;
        uint32_t bbuf = abuf + BM * AS_STRIDE * 4;
#pragma unroll
        for (int it = 0; it < 4; it++) {
            int idx = tid + it * 256;
            int row = idx >> 3, c4 = (idx & 7) * 4;
            cp16(abuf + (uint32_t)(row * AS_STRIDE + c4) * 4,
                 Abase + (size_t)row * FF + k0 + c4);
        }
#pragma unroll
        for (int it = 0; it < 8; it++) {
            int idx = tid + it * 256;
            int kr = idx >> 6, f4 = (idx & 63) * 4;
            cp16(bbuf + (uint32_t)(kr * BS_STRIDE + f4) * 4,
                 W + (size_t)(k0 + kr) * FF + f4);
        }
    };

    stage(0, 0);
    cp_commit();

#pragma unroll
    for (int kt = 0; kt < FF / BK; kt++) {
        if (kt + 1 < FF / BK) {
            stage((kt + 1) & 1, kt + 1);
            cp_commit();
            asm volatile("cp.async.wait_group 1;");
        } else {
            asm volatile("cp.async.wait_group 0;");
        }
        __syncthreads();

        const float* As = smem + (kt & 1) * BUF_FLOATS;
        const float* Bs = As + BM * AS_STRIDE;

#pragma unroll
        for (int k8 = 0; k8 < BK / 8; k8++) {
            int kk = k8 * 8;
            uint32_t afr[4][4], bfr[8][2];
#pragma unroll
            for (int mt = 0; mt < 4; mt++) {
                int m = wm * 64 + mt * 16;
                afr[mt][0] = __float_as_uint(As[(m + g)     * AS_STRIDE + kk + tg]);
                afr[mt][1] = __float_as_uint(As[(m + g + 8) * AS_STRIDE + kk + tg]);
                afr[mt][2] = __float_as_uint(As[(m + g)     * AS_STRIDE + kk + tg + 4]);
                afr[mt][3] = __float_as_uint(As[(m + g + 8) * AS_STRIDE + kk + tg + 4]);
            }
#pragma unroll
            for (int nt = 0; nt < 8; nt++) {
                int f = wn * 64 + nt * 8 + g;
                bfr[nt][0] = __float_as_uint(Bs[(kk + tg)     * BS_STRIDE + f]);
                bfr[nt][1] = __float_as_uint(Bs[(kk + tg + 4) * BS_STRIDE + f]);
            }
#pragma unroll
            for (int mt = 0; mt < 4; mt++)
#pragma unroll
                for (int nt = 0; nt < 8; nt++)
                    mma_tf32(acc[mt][nt], afr[mt], bfr[nt]);
        }
        __syncthreads();
    }

    // epilogue: write support
#pragma unroll
    for (int mt = 0; mt < 4; mt++) {
        int m = wm * 64 + mt * 16;
#pragma unroll
        for (int nt = 0; nt < 8; nt++) {
            int f = wn * 64 + nt * 8 + 2 * tg;
            *(float2*)(g_sup + (size_t)(b0 + m + g)     * FF + f) =
                make_float2(acc[mt][nt][0], acc[mt][nt][1]);
            *(float2*)(g_sup + (size_t)(b0 + m + g + 8) * FF + f) =
                make_float2(acc[mt][nt][2], acc[mt][nt][3]);
        }
    }
}

// ---------------- kstats: recompute bmm, accumulate batch stats ----------------
#define STAT_CHUNK 64
__global__ void __launch_bounds__(256) kstats(const float* __restrict__ adj) {
    int blk = blockIdx.x, s = blk * BLKC;
    int b0  = blockIdx.y * STAT_CHUNK;
    int f   = threadIdx.x;
    __shared__ float s_adj[BLKC][BLKC];

    float sum[BLKC], sq[BLKC];
#pragma unroll
    for (int r = 0; r < BLKC; r++) { sum[r] = 0.f; sq[r] = 0.f; }

    for (int bi = 0; bi < STAT_CHUNK; bi++) {
        int b = b0 + bi;
        if (f < BLKC * BLKC)
            s_adj[f / BLKC][f % BLKC] = adj[((size_t)b * NN + s + f / BLKC) * NN + s + f % BLKC];
        float xin[BLKC];
        const float* sp = g_sup + ((size_t)b * NN + s) * FF + f;
#pragma unroll
        for (int j = 0; j < BLKC; j++) xin[j] = sp[(size_t)j * FF];
        __syncthreads();
#pragma unroll
        for (int r = 0; r < BLKC; r++) {
            float y = 0.f;
#pragma unroll
            for (int j = 0; j < BLKC; j++) y += s_adj[r][j] * xin[j];
            sum[r] += y;
            sq[r]  += y * y;
        }
        __syncthreads();
    }
#pragma unroll
    for (int r = 0; r < BLKC; r++) {
        atomicAdd(&g_sum[(s + r) * FF + f],   sum[r]);
        atomicAdd(&g_sumsq[(s + r) * FF + f], sq[r]);
    }
}

// ---------------- k3: fold BN into per-feature affine (a, c) ----------------
__global__ void k3_coeff(const float* __restrict__ gamma, const float* __restrict__ beta) {
    int idx = blockIdx.x * 256 + threadIdx.x;
    if (idx >= NN * FF) return;
    int nrow = idx / FF;
    int blk  = nrow / BLKC;
    float mean = g_sum[idx] * (1.f / B_);
    float var  = g_sumsq[idx] * (1.f / B_) - mean * mean;
    float a = gamma[(size_t)blk * (NN * FF) + idx] * rsqrtf(var + 1e-5f);
    float bsum = 0.f;
#pragma unroll
    for (int i = 0; i < NBLKC; i++) bsum += beta[(size_t)i * (NN * FF) + idx];
    g_a[idx] = a;
    g_c[idx] = bsum - mean * a;
}

// ---------------- k4: recompute bmm, apply affine, write out ----------------
#define OUT_CHUNK 16
__global__ void __launch_bounds__(256) k4_out(const float* __restrict__ adj,
                                              float* __restrict__ out) {
    int blk = blockIdx.x, s = blk * BLKC;
    int b0  = blockIdx.y * OUT_CHUNK;
    int f   = threadIdx.x;
    __shared__ float s_adj[BLKC][BLKC];

    float ar[BLKC], cr[BLKC];
#pragma unroll
    for (int r = 0; r < BLKC; r++) {
        ar[r] = g_a[(s + r) * FF + f];
        cr[r] = g_c[(s + r) * FF + f];
    }

    for (int bi = 0; bi < OUT_CHUNK; bi++) {
        int b = b0 + bi;
        if (f < BLKC * BLKC)
            s_adj[f / BLKC][f % BLKC] = adj[((size_t)b * NN + s + f / BLKC) * NN + s + f % BLKC];
        float xin[BLKC];
        const float* sp = g_sup + ((size_t)b * NN + s) * FF + f;
#pragma unroll
        for (int j = 0; j < BLKC; j++) xin[j] = sp[(size_t)j * FF];
        __syncthreads();
#pragma unroll
        for (int r = 0; r < BLKC; r++) {
            float y = 0.f;
#pragma unroll
            for (int j = 0; j < BLKC; j++) y += s_adj[r][j] * xin[j];
            out[((size_t)b * NN + s + r) * FF + f] = y * ar[r] + cr[r];
        }
        __syncthreads();
    }
}

// ---------------- launch ----------------
extern "C" void kernel_launch(void* const* d_in, const int* in_sizes, int n_in,
                              void* d_out, int out_size) {
    const float* input = (const float*)d_in[0];
    const float* adj   = (const float*)d_in[1];
    const float* W     = (const float*)d_in[2];
    const float* gamma = (const float*)d_in[3];
    const float* beta  = (const float*)d_in[4];
    float* out = (float*)d_out;

    cudaFuncSetAttribute(k2_gemm, cudaFuncAttributeMaxDynamicSharedMemorySize, K2_SMEM_BYTES);

    k0_zero<<<(NN * FF + 255) / 256, 256>>>();
    k2_gemm<<<(B_ * NN) / BM, 256, K2_SMEM_BYTES>>>(input, W);
    kstats<<<dim3(NBLKC, B_ / STAT_CHUNK), 256>>>(adj);
    k3_coeff<<<(NN * FF + 255) / 256, 256>>>(gamma, beta);
    k4_out<<<dim3(NBLKC, B_ / OUT_CHUNK), 256>>>(adj, out);
}